// round 1
// baseline (speedup 1.0000x reference)
#include <cuda_runtime.h>
#include <cuda_bf16.h>
#include <cstdint>

// Problem constants (shape-fixed)
#define T_SEQ   2048
#define HID     4096
#define NQH     32
#define NKVH    2
#define HD      128
#define QKV_OUT ((NQH + 2*NKVH) * HD)   // 4608
#define Q_SZ    (NQH * HD)              // 4096
#define KV_SZ   (NKVH * HD)             // 256
#define GROUP   (NQH / NKVH)            // 16
#define ROPE_PAIRS 32                   // ROPE_DIM/2

// Scratch (allocation-free rule: __device__ globals)
__device__ float g_qkv [T_SEQ * QKV_OUT];   // [2048, 4608]
__device__ float g_attn[T_SEQ * Q_SZ];      // [2048, 4096]

// ---------------------------------------------------------------------------
// SGEMM: C[M,N] = A[M,K] @ B[K,N] (+bias). 128x128 tile, BK=16, 256 thr, 8x8/thr
// ---------------------------------------------------------------------------
__global__ __launch_bounds__(256)
void sgemm_kernel(const float* __restrict__ A, const float* __restrict__ B,
                  const float* __restrict__ bias, float* __restrict__ C,
                  int M, int N, int K)
{
    __shared__ float As[16 * 132];  // A^T tile: As[k][m], padded stride 132
    __shared__ float Bs[16 * 128];  // Bs[k][n]

    const int tid = threadIdx.x;
    const int tx  = tid & 15;
    const int ty  = tid >> 4;
    const int bm  = blockIdx.y * 128;
    const int bn  = blockIdx.x * 128;

    float acc[8][8];
    #pragma unroll
    for (int i = 0; i < 8; i++)
        #pragma unroll
        for (int j = 0; j < 8; j++) acc[i][j] = 0.f;

    for (int k0 = 0; k0 < K; k0 += 16) {
        // Load A tile (128x16) transposed, B tile (16x128) straight
        #pragma unroll
        for (int t = 0; t < 2; t++) {
            int f = tid + t * 256;                 // 0..511 float4 slots
            // A: row = f/4, 4 k's at (f%4)*4
            int r  = f >> 2;
            int kq = (f & 3) << 2;
            float4 a = *(const float4*)&A[(size_t)(bm + r) * K + k0 + kq];
            As[(kq + 0) * 132 + r] = a.x;
            As[(kq + 1) * 132 + r] = a.y;
            As[(kq + 2) * 132 + r] = a.z;
            As[(kq + 3) * 132 + r] = a.w;
            // B: row = f/32, col4 = f%32
            int rb = f >> 5;
            int c4 = (f & 31) << 2;
            *(float4*)&Bs[rb * 128 + c4] =
                *(const float4*)&B[(size_t)(k0 + rb) * N + bn + c4];
        }
        __syncthreads();

        #pragma unroll
        for (int k = 0; k < 16; k++) {
            float4 a0 = *(float4*)&As[k * 132 + 8 * ty];
            float4 a1 = *(float4*)&As[k * 132 + 8 * ty + 4];
            float4 b0 = *(float4*)&Bs[k * 128 + 8 * tx];
            float4 b1 = *(float4*)&Bs[k * 128 + 8 * tx + 4];
            float av[8] = {a0.x, a0.y, a0.z, a0.w, a1.x, a1.y, a1.z, a1.w};
            float bv[8] = {b0.x, b0.y, b0.z, b0.w, b1.x, b1.y, b1.z, b1.w};
            #pragma unroll
            for (int i = 0; i < 8; i++)
                #pragma unroll
                for (int j = 0; j < 8; j++)
                    acc[i][j] = fmaf(av[i], bv[j], acc[i][j]);
        }
        __syncthreads();
    }

    // Epilogue
    #pragma unroll
    for (int i = 0; i < 8; i++) {
        int row = bm + 8 * ty + i;
        #pragma unroll
        for (int jj = 0; jj < 8; jj += 4) {
            int col = bn + 8 * tx + jj;
            float4 r;
            if (bias) {
                r.x = acc[i][jj + 0] + bias[col + 0];
                r.y = acc[i][jj + 1] + bias[col + 1];
                r.z = acc[i][jj + 2] + bias[col + 2];
                r.w = acc[i][jj + 3] + bias[col + 3];
            } else {
                r.x = acc[i][jj + 0]; r.y = acc[i][jj + 1];
                r.z = acc[i][jj + 2]; r.w = acc[i][jj + 3];
            }
            *(float4*)&C[(size_t)row * N + col] = r;
        }
    }
}

// ---------------------------------------------------------------------------
// RoPE in-place on g_qkv. Net permutation of extract/fill = interleaved pairs:
//   pair p: (x[2p], x[2p+1]) rotated by ang_p; cos/sin arrays give cos at col p.
// Applies to first 64 dims of every q head (32) and k head (2).
// ---------------------------------------------------------------------------
__global__ __launch_bounds__(256)
void rope_kernel(float* __restrict__ qkv, const float* __restrict__ cosb,
                 const float* __restrict__ sinb)
{
    int id = blockIdx.x * blockDim.x + threadIdx.x;
    const int total = T_SEQ * (NQH + NKVH) * ROPE_PAIRS;
    if (id >= total) return;
    int p    = id & 31;
    int head = (id >> 5) % (NQH + NKVH);
    int t    = id / ((NQH + NKVH) * ROPE_PAIRS);

    int base = (head < NQH) ? head * HD : Q_SZ + (head - NQH) * HD;
    float* x = qkv + (size_t)t * QKV_OUT + base;
    float c = cosb[t * 64 + p];
    float s = sinb[t * 64 + p];
    float x0 = x[2 * p];
    float x1 = x[2 * p + 1];
    x[2 * p]     = x0 * c - x1 * s;
    x[2 * p + 1] = x1 * c + x0 * s;
}

// ---------------------------------------------------------------------------
// Flash attention, causal, GQA. BQ=BK=64, D=128, 256 threads.
// blockIdx.x = q tile, blockIdx.y = head.
// Smem: Qt[128][68], Kt[128][68] (d-major), Vs[64][128], Ps[64][65].
// ---------------------------------------------------------------------------
#define FL_SMEM_FLOATS (2 * 128 * 68 + 64 * 128 + 64 * 65)
#define FL_SMEM_BYTES  (FL_SMEM_FLOATS * 4)

__global__ __launch_bounds__(256)
void flash_kernel(const float* __restrict__ qkv, float* __restrict__ attn)
{
    extern __shared__ float sm[];
    float* Qt = sm;                          // [d][row] stride 68
    float* Kt = sm + 128 * 68;               // [d][col] stride 68
    float* Vs = sm + 2 * 128 * 68;           // [row][d] stride 128
    float* Ps = sm + 2 * 128 * 68 + 64 * 128;// [row][col] stride 65

    const int qt = blockIdx.x;
    const int h  = blockIdx.y;
    const int q0 = qt * 64;
    const int kvh = h >> 4;                  // GROUP = 16
    const int tid = threadIdx.x;
    const int tx = tid & 15;
    const int ty = tid >> 4;

    const int qcol = h * HD;
    const int kcol = Q_SZ + kvh * HD;
    const int vcol = Q_SZ + KV_SZ + kvh * HD;
    const float scale = 0.08838834764831845f;   // 1/sqrt(128)

    // Load Q tile transposed
    #pragma unroll
    for (int t = 0; t < 8; t++) {
        int f  = tid + t * 256;          // 0..2047
        int r  = f >> 5;
        int d4 = (f & 31) << 2;
        float4 v = *(const float4*)&qkv[(size_t)(q0 + r) * QKV_OUT + qcol + d4];
        Qt[(d4 + 0) * 68 + r] = v.x;
        Qt[(d4 + 1) * 68 + r] = v.y;
        Qt[(d4 + 2) * 68 + r] = v.z;
        Qt[(d4 + 3) * 68 + r] = v.w;
    }

    float o[4][8];
    #pragma unroll
    for (int i = 0; i < 4; i++)
        #pragma unroll
        for (int c = 0; c < 8; c++) o[i][c] = 0.f;
    float mrow[4] = {-1e30f, -1e30f, -1e30f, -1e30f};
    float lrow[4] = {0.f, 0.f, 0.f, 0.f};

    const int ntiles = qt + 1;
    for (int j = 0; j < ntiles; j++) {
        const int k0 = j * 64;
        __syncthreads();   // protect Kt/Vs/Ps reuse (also orders first Qt use)

        // Load K tile transposed + V tile straight
        #pragma unroll
        for (int t = 0; t < 8; t++) {
            int f  = tid + t * 256;
            int r  = f >> 5;
            int d4 = (f & 31) << 2;
            float4 kv4 = *(const float4*)&qkv[(size_t)(k0 + r) * QKV_OUT + kcol + d4];
            Kt[(d4 + 0) * 68 + r] = kv4.x;
            Kt[(d4 + 1) * 68 + r] = kv4.y;
            Kt[(d4 + 2) * 68 + r] = kv4.z;
            Kt[(d4 + 3) * 68 + r] = kv4.w;
            float4 vv = *(const float4*)&qkv[(size_t)(k0 + r) * QKV_OUT + vcol + d4];
            *(float4*)&Vs[r * 128 + d4] = vv;
        }
        __syncthreads();

        // S = Q @ K^T : s[4 rows][4 cols] per thread
        float s[4][4];
        #pragma unroll
        for (int i = 0; i < 4; i++)
            #pragma unroll
            for (int jj = 0; jj < 4; jj++) s[i][jj] = 0.f;

        #pragma unroll 4
        for (int d = 0; d < 128; d++) {
            float4 a4 = *(float4*)&Qt[d * 68 + 4 * ty];
            float4 b4 = *(float4*)&Kt[d * 68 + 4 * tx];
            float av[4] = {a4.x, a4.y, a4.z, a4.w};
            float bv[4] = {b4.x, b4.y, b4.z, b4.w};
            #pragma unroll
            for (int i = 0; i < 4; i++)
                #pragma unroll
                for (int jj = 0; jj < 4; jj++)
                    s[i][jj] = fmaf(av[i], bv[jj], s[i][jj]);
        }

        const bool diag = (j == qt);
        #pragma unroll
        for (int i = 0; i < 4; i++) {
            #pragma unroll
            for (int jj = 0; jj < 4; jj++) {
                float val = s[i][jj] * scale;
                if (diag && (k0 + 4 * tx + jj > q0 + 4 * ty + i)) val = -1e30f;
                s[i][jj] = val;
            }
        }

        // Online softmax per row (reduce across the 16 tx lanes)
        #pragma unroll
        for (int i = 0; i < 4; i++) {
            float mloc = fmaxf(fmaxf(s[i][0], s[i][1]), fmaxf(s[i][2], s[i][3]));
            #pragma unroll
            for (int off = 8; off >= 1; off >>= 1)
                mloc = fmaxf(mloc, __shfl_xor_sync(0xffffffffu, mloc, off, 16));
            float mnew  = fmaxf(mrow[i], mloc);
            float alpha = __expf(mrow[i] - mnew);
            float psum = 0.f;
            #pragma unroll
            for (int jj = 0; jj < 4; jj++) {
                float p = __expf(s[i][jj] - mnew);
                s[i][jj] = p;
                psum += p;
            }
            #pragma unroll
            for (int off = 8; off >= 1; off >>= 1)
                psum += __shfl_xor_sync(0xffffffffu, psum, off, 16);
            lrow[i] = lrow[i] * alpha + psum;
            mrow[i] = mnew;
            #pragma unroll
            for (int c = 0; c < 8; c++) o[i][c] *= alpha;
            #pragma unroll
            for (int jj = 0; jj < 4; jj++)
                Ps[(4 * ty + i) * 65 + 4 * tx + jj] = s[i][jj];
        }
        __syncthreads();

        // O += P @ V
        #pragma unroll 2
        for (int kk = 0; kk < 64; kk++) {
            float4 v0 = *(float4*)&Vs[kk * 128 + 8 * tx];
            float4 v1 = *(float4*)&Vs[kk * 128 + 8 * tx + 4];
            float pv[4];
            #pragma unroll
            for (int i = 0; i < 4; i++) pv[i] = Ps[(4 * ty + i) * 65 + kk];
            #pragma unroll
            for (int i = 0; i < 4; i++) {
                o[i][0] = fmaf(pv[i], v0.x, o[i][0]);
                o[i][1] = fmaf(pv[i], v0.y, o[i][1]);
                o[i][2] = fmaf(pv[i], v0.z, o[i][2]);
                o[i][3] = fmaf(pv[i], v0.w, o[i][3]);
                o[i][4] = fmaf(pv[i], v1.x, o[i][4]);
                o[i][5] = fmaf(pv[i], v1.y, o[i][5]);
                o[i][6] = fmaf(pv[i], v1.z, o[i][6]);
                o[i][7] = fmaf(pv[i], v1.w, o[i][7]);
            }
        }
    }

    // Epilogue: normalize + store to g_attn [T, 32*128]
    #pragma unroll
    for (int i = 0; i < 4; i++) {
        float inv = 1.f / lrow[i];
        int row = q0 + 4 * ty + i;
        float* dst = attn + (size_t)row * Q_SZ + h * HD + 8 * tx;
        float4 r0, r1;
        r0.x = o[i][0] * inv; r0.y = o[i][1] * inv;
        r0.z = o[i][2] * inv; r0.w = o[i][3] * inv;
        r1.x = o[i][4] * inv; r1.y = o[i][5] * inv;
        r1.z = o[i][6] * inv; r1.w = o[i][7] * inv;
        *(float4*)&dst[0] = r0;
        *(float4*)&dst[4] = r1;
    }
}

// ---------------------------------------------------------------------------
extern "C" void kernel_launch(void* const* d_in, const int* in_sizes, int n_in,
                              void* d_out, int out_size)
{
    const float* hidden  = (const float*)d_in[0];
    const float* cosb    = (const float*)d_in[1];
    const float* sinb    = (const float*)d_in[2];
    const float* W_qkv   = (const float*)d_in[3];
    const float* b_qkv   = (const float*)d_in[4];
    const float* W_dense = (const float*)d_in[5];
    float* out = (float*)d_out;

    float* qkv;  cudaGetSymbolAddress((void**)&qkv,  g_qkv);
    float* attn; cudaGetSymbolAddress((void**)&attn, g_attn);

    // 1) QKV projection + bias
    {
        dim3 grid(QKV_OUT / 128, T_SEQ / 128);
        sgemm_kernel<<<grid, 256>>>(hidden, W_qkv, b_qkv, qkv,
                                    T_SEQ, QKV_OUT, HID);
    }

    // 2) RoPE in place
    {
        int total = T_SEQ * (NQH + NKVH) * ROPE_PAIRS;
        rope_kernel<<<(total + 255) / 256, 256>>>(qkv, cosb, sinb);
    }

    // 3) Flash attention
    {
        static int smem_set = 0;
        cudaFuncSetAttribute(flash_kernel,
                             cudaFuncAttributeMaxDynamicSharedMemorySize,
                             FL_SMEM_BYTES);
        (void)smem_set;
        dim3 grid(T_SEQ / 64, NQH);
        flash_kernel<<<grid, 256, FL_SMEM_BYTES>>>(qkv, attn);
    }

    // 4) Dense projection
    {
        dim3 grid(HID / 128, T_SEQ / 128);
        sgemm_kernel<<<grid, 256>>>(attn, W_dense, nullptr, out,
                                    T_SEQ, HID, Q_SZ);
    }
}

// round 3
// speedup vs baseline: 1.4812x; 1.4812x over previous
#include <cuda_runtime.h>
#include <cuda_bf16.h>
#include <cstdint>

// ===========================================================================
// Problem constants
// ===========================================================================
#define T_SEQ   2048
#define HID     4096
#define NQH     32
#define NKVH    2
#define HD      128
#define QKV_OUT ((NQH + 2*NKVH) * HD)   // 4608
#define Q_SZ    (NQH * HD)              // 4096
#define KV_SZ   (NKVH * HD)             // 256
#define ROPE_PAIRS 32

// ===========================================================================
// Scratch (__device__ globals; allocation-free rule)
// ===========================================================================
__device__ float         g_qkv [T_SEQ * QKV_OUT];
__device__ __nv_bfloat16 g_Ah_hi[T_SEQ * HID];
__device__ __nv_bfloat16 g_Ah_lo[T_SEQ * HID];
__device__ __nv_bfloat16 g_Wq_hi[QKV_OUT * HID];   // W_qkv^T  [N,K]
__device__ __nv_bfloat16 g_Wq_lo[QKV_OUT * HID];
__device__ __nv_bfloat16 g_Wd_hi[HID * Q_SZ];      // W_dense^T [N,K]
__device__ __nv_bfloat16 g_Wd_lo[HID * Q_SZ];
__device__ __nv_bfloat16 g_at_hi[T_SEQ * Q_SZ];
__device__ __nv_bfloat16 g_at_lo[T_SEQ * Q_SZ];

// ===========================================================================
// Helpers
// ===========================================================================
__device__ __forceinline__ uint32_t smem_u32(const void* p) {
    uint32_t a;
    asm("{ .reg .u64 t; cvta.to.shared.u64 t, %1; cvt.u32.u64 %0, t; }"
        : "=r"(a) : "l"(p));
    return a;
}
__device__ __forceinline__ void cpa16(uint32_t dst, const void* src) {
    asm volatile("cp.async.cg.shared.global [%0], [%1], 16;" :: "r"(dst), "l"(src));
}
#define CP_COMMIT() asm volatile("cp.async.commit_group;" ::: "memory")
#define CP_WAIT(n)  asm volatile("cp.async.wait_group %0;" :: "n"(n) : "memory")

__device__ __forceinline__ void ldm_x4(uint32_t* r, uint32_t addr) {
    asm volatile("ldmatrix.sync.aligned.m8n8.x4.shared.b16 {%0,%1,%2,%3}, [%4];"
                 : "=r"(r[0]), "=r"(r[1]), "=r"(r[2]), "=r"(r[3]) : "r"(addr));
}
__device__ __forceinline__ void ldm_x2(uint32_t* r, uint32_t addr) {
    asm volatile("ldmatrix.sync.aligned.m8n8.x2.shared.b16 {%0,%1}, [%2];"
                 : "=r"(r[0]), "=r"(r[1]) : "r"(addr));
}
__device__ __forceinline__ void mma_bf16(float* c, const uint32_t* a, const uint32_t* b) {
    asm volatile(
        "mma.sync.aligned.m16n8k16.row.col.f32.bf16.bf16.f32 "
        "{%0,%1,%2,%3}, {%4,%5,%6,%7}, {%8,%9}, {%0,%1,%2,%3};"
        : "+f"(c[0]), "+f"(c[1]), "+f"(c[2]), "+f"(c[3])
        : "r"(a[0]), "r"(a[1]), "r"(a[2]), "r"(a[3]), "r"(b[0]), "r"(b[1]));
}

// ===========================================================================
// Prep: fp32 -> bf16 hi/lo splits
// ===========================================================================
__global__ __launch_bounds__(256)
void split_kernel(const float4* __restrict__ X, __nv_bfloat16* __restrict__ hi,
                  __nv_bfloat16* __restrict__ lo, int n4)
{
    int i = blockIdx.x * blockDim.x + threadIdx.x;
    if (i >= n4) return;
    float4 v = X[i];
    __nv_bfloat16 hx = __float2bfloat16(v.x), hy = __float2bfloat16(v.y);
    __nv_bfloat16 hz = __float2bfloat16(v.z), hw = __float2bfloat16(v.w);
    __nv_bfloat162 h0; h0.x = hx; h0.y = hy;
    __nv_bfloat162 h1; h1.x = hz; h1.y = hw;
    __nv_bfloat162 l0, l1;
    l0.x = __float2bfloat16(v.x - __bfloat162float(hx));
    l0.y = __float2bfloat16(v.y - __bfloat162float(hy));
    l1.x = __float2bfloat16(v.z - __bfloat162float(hz));
    l1.y = __float2bfloat16(v.w - __bfloat162float(hw));
    ((__nv_bfloat162*)hi)[2*i]   = h0;
    ((__nv_bfloat162*)hi)[2*i+1] = h1;
    ((__nv_bfloat162*)lo)[2*i]   = l0;
    ((__nv_bfloat162*)lo)[2*i+1] = l1;
}

// W [K,N] row-major -> out [N,K] bf16 hi/lo
__global__ __launch_bounds__(256)
void transpose_split_kernel(const float* __restrict__ W,
                            __nv_bfloat16* __restrict__ hi,
                            __nv_bfloat16* __restrict__ lo, int K, int N)
{
    __shared__ float t[32][33];
    int n0 = blockIdx.x * 32, k0 = blockIdx.y * 32;
    int tx = threadIdx.x, ty = threadIdx.y;   // 32 x 8
    #pragma unroll
    for (int i = ty; i < 32; i += 8)
        t[i][tx] = W[(size_t)(k0 + i) * N + n0 + tx];
    __syncthreads();
    #pragma unroll
    for (int i = ty; i < 32; i += 8) {
        float v = t[tx][i];
        __nv_bfloat16 h = __float2bfloat16(v);
        size_t o = (size_t)(n0 + i) * K + k0 + tx;
        hi[o] = h;
        lo[o] = __float2bfloat16(v - __bfloat162float(h));
    }
}

// ===========================================================================
// HMMA bf16x3 GEMM: C[M,N] = (Ahi+Alo)[M,K] @ (Bhi+Blo)^T ([N,K] K-major)
// CTA tile 128x128, BK=32, 256 thr (8 warps, warp tile 64x32), cp.async x2 buf.
// Smem stage: 4 tiles of [128][40] bf16 (80B stride; ldmatrix conflict-free).
// ===========================================================================
#define SA_BYTES   80                       // 32 bf16 + 8 pad
#define TILE_BYTES (128 * SA_BYTES)         // 10240
#define STAGE_BYTES (4 * TILE_BYTES)        // 40960
#define GEMM_SMEM   (2 * STAGE_BYTES)       // 81920

__device__ __forceinline__ void issue_stage(uint32_t sbase,
        const __nv_bfloat16* __restrict__ Ahi, const __nv_bfloat16* __restrict__ Alo,
        const __nv_bfloat16* __restrict__ Bhi, const __nv_bfloat16* __restrict__ Blo,
        int m0, int n0, int K, int k0)
{
    const int tid = threadIdx.x;
    #pragma unroll
    for (int i = 0; i < 2; i++) {
        int c   = tid + i * 256;         // 0..511
        int r   = c >> 2;                // row 0..127
        int seg = c & 3;                 // 16B segment
        uint32_t doff = r * SA_BYTES + seg * 16;
        size_t  ga = (size_t)(m0 + r) * K + k0 + seg * 8;
        size_t  gb = (size_t)(n0 + r) * K + k0 + seg * 8;
        cpa16(sbase + doff,                  &Ahi[ga]);
        cpa16(sbase + TILE_BYTES + doff,     &Alo[ga]);
        cpa16(sbase + 2 * TILE_BYTES + doff, &Bhi[gb]);
        cpa16(sbase + 3 * TILE_BYTES + doff, &Blo[gb]);
    }
    CP_COMMIT();
}

__global__ __launch_bounds__(256, 1)
void hmma_gemm(const __nv_bfloat16* __restrict__ Ahi, const __nv_bfloat16* __restrict__ Alo,
               const __nv_bfloat16* __restrict__ Bhi, const __nv_bfloat16* __restrict__ Blo,
               const float* __restrict__ bias, float* __restrict__ C,
               int M, int N, int K)
{
    extern __shared__ __align__(128) char sm_raw[];
    const uint32_t sbase = smem_u32(sm_raw);
    const int tid  = threadIdx.x;
    const int lane = tid & 31;
    const int warp = tid >> 5;
    const int wm   = (warp >> 2) * 64;   // warp row offset (0 / 64)
    const int wn   = (warp & 3) * 32;    // warp col offset (0..96)
    const int m0 = blockIdx.y * 128;
    const int n0 = blockIdx.x * 128;

    // ldmatrix per-lane base offsets (within a tile)
    const uint32_t a_off = (uint32_t)(wm + (lane & 15)) * SA_BYTES + ((lane >> 4) * 8) * 2;
    const int bl = lane & 15;
    const uint32_t b_off = (uint32_t)(wn + (bl & 7)) * SA_BYTES + (((bl >> 3) & 1) * 8) * 2;

    float acc[4][4][4];
    #pragma unroll
    for (int i = 0; i < 4; i++)
        #pragma unroll
        for (int j = 0; j < 4; j++)
            #pragma unroll
            for (int c = 0; c < 4; c++) acc[i][j][c] = 0.f;

    issue_stage(sbase, Ahi, Alo, Bhi, Blo, m0, n0, K, 0);

    const int nch = K / 32;
    for (int j = 0; j < nch; j++) {
        const uint32_t sb = sbase + (j & 1) * STAGE_BYTES;
        if (j + 1 < nch) {
            issue_stage(sbase + ((j + 1) & 1) * STAGE_BYTES,
                        Ahi, Alo, Bhi, Blo, m0, n0, K, (j + 1) * 32);
            CP_WAIT(1);
        } else {
            CP_WAIT(0);
        }
        __syncthreads();

        const uint32_t aaddr = sb + a_off;                   // A hi tile
        const uint32_t baddr = sb + 2 * TILE_BYTES + b_off;  // B hi tile
        #pragma unroll
        for (int kk = 0; kk < 2; kk++) {
            const uint32_t ko = kk * 32;   // 16 bf16 cols = 32B
            uint32_t ah[4][4], al[4][4], bh[4][2], blo_[4][2];
            #pragma unroll
            for (int mi = 0; mi < 4; mi++) {
                ldm_x4(ah[mi], aaddr + mi * (16 * SA_BYTES) + ko);
                ldm_x4(al[mi], aaddr + TILE_BYTES + mi * (16 * SA_BYTES) + ko);
            }
            #pragma unroll
            for (int ni = 0; ni < 4; ni++) {
                ldm_x2(bh[ni],   baddr + ni * (8 * SA_BYTES) + ko);
                ldm_x2(blo_[ni], baddr + TILE_BYTES + ni * (8 * SA_BYTES) + ko);
            }
            #pragma unroll
            for (int mi = 0; mi < 4; mi++)
                #pragma unroll
                for (int ni = 0; ni < 4; ni++) {
                    mma_bf16(acc[mi][ni], ah[mi], bh[ni]);
                    mma_bf16(acc[mi][ni], ah[mi], blo_[ni]);
                    mma_bf16(acc[mi][ni], al[mi], bh[ni]);
                }
        }
        __syncthreads();
    }

    // Epilogue: fp32 + bias
    const int g = lane >> 2;
    const int t2 = (lane & 3) * 2;
    #pragma unroll
    for (int mi = 0; mi < 4; mi++) {
        #pragma unroll
        for (int ni = 0; ni < 4; ni++) {
            int row = m0 + wm + mi * 16 + g;
            int col = n0 + wn + ni * 8 + t2;
            float b0 = bias ? bias[col]     : 0.f;
            float b1 = bias ? bias[col + 1] : 0.f;
            float2 v0 = make_float2(acc[mi][ni][0] + b0, acc[mi][ni][1] + b1);
            float2 v1 = make_float2(acc[mi][ni][2] + b0, acc[mi][ni][3] + b1);
            *(float2*)&C[(size_t)row * N + col]       = v0;
            *(float2*)&C[(size_t)(row + 8) * N + col] = v1;
        }
    }
}

// ===========================================================================
// RoPE in place (interleaved-pair rotation)
// ===========================================================================
__global__ __launch_bounds__(256)
void rope_kernel(float* __restrict__ qkv, const float* __restrict__ cosb,
                 const float* __restrict__ sinb)
{
    int id = blockIdx.x * blockDim.x + threadIdx.x;
    const int total = T_SEQ * (NQH + NKVH) * ROPE_PAIRS;
    if (id >= total) return;
    int p    = id & 31;
    int head = (id >> 5) % (NQH + NKVH);
    int t    = id / ((NQH + NKVH) * ROPE_PAIRS);

    int base = (head < NQH) ? head * HD : Q_SZ + (head - NQH) * HD;
    float* x = qkv + (size_t)t * QKV_OUT + base;
    float c = cosb[t * 64 + p];
    float s = sinb[t * 64 + p];
    float x0 = x[2 * p];
    float x1 = x[2 * p + 1];
    x[2 * p]     = x0 * c - x1 * s;
    x[2 * p + 1] = x1 * c + x0 * s;
}

// ===========================================================================
// Flash attention (fp32 FFMA, proven R1 body), bf16 hi/lo output
// ===========================================================================
#define FL_SMEM_FLOATS (2 * 128 * 68 + 64 * 128 + 64 * 65)
#define FL_SMEM_BYTES  (FL_SMEM_FLOATS * 4)

__global__ __launch_bounds__(256)
void flash_kernel(const float* __restrict__ qkv,
                  __nv_bfloat16* __restrict__ out_hi,
                  __nv_bfloat16* __restrict__ out_lo)
{
    extern __shared__ float sm[];
    float* Qt = sm;                           // [d][row] stride 68
    float* Kt = sm + 128 * 68;                // [d][col] stride 68
    float* Vs = sm + 2 * 128 * 68;            // [row][d] stride 128
    float* Ps = sm + 2 * 128 * 68 + 64 * 128; // [row][col] stride 65

    const int qt = blockIdx.x;
    const int h  = blockIdx.y;
    const int q0 = qt * 64;
    const int kvh = h >> 4;
    const int tid = threadIdx.x;
    const int tx = tid & 15;
    const int ty = tid >> 4;

    const int qcol = h * HD;
    const int kcol = Q_SZ + kvh * HD;
    const int vcol = Q_SZ + KV_SZ + kvh * HD;
    const float scale = 0.08838834764831845f;

    #pragma unroll
    for (int t = 0; t < 8; t++) {
        int f  = tid + t * 256;
        int r  = f >> 5;
        int d4 = (f & 31) << 2;
        float4 v = *(const float4*)&qkv[(size_t)(q0 + r) * QKV_OUT + qcol + d4];
        Qt[(d4 + 0) * 68 + r] = v.x;
        Qt[(d4 + 1) * 68 + r] = v.y;
        Qt[(d4 + 2) * 68 + r] = v.z;
        Qt[(d4 + 3) * 68 + r] = v.w;
    }

    float o[4][8];
    #pragma unroll
    for (int i = 0; i < 4; i++)
        #pragma unroll
        for (int c = 0; c < 8; c++) o[i][c] = 0.f;
    float mrow[4] = {-1e30f, -1e30f, -1e30f, -1e30f};
    float lrow[4] = {0.f, 0.f, 0.f, 0.f};

    const int ntiles = qt + 1;
    for (int j = 0; j < ntiles; j++) {
        const int k0 = j * 64;
        __syncthreads();

        #pragma unroll
        for (int t = 0; t < 8; t++) {
            int f  = tid + t * 256;
            int r  = f >> 5;
            int d4 = (f & 31) << 2;
            float4 kv4 = *(const float4*)&qkv[(size_t)(k0 + r) * QKV_OUT + kcol + d4];
            Kt[(d4 + 0) * 68 + r] = kv4.x;
            Kt[(d4 + 1) * 68 + r] = kv4.y;
            Kt[(d4 + 2) * 68 + r] = kv4.z;
            Kt[(d4 + 3) * 68 + r] = kv4.w;
            float4 vv = *(const float4*)&qkv[(size_t)(k0 + r) * QKV_OUT + vcol + d4];
            *(float4*)&Vs[r * 128 + d4] = vv;
        }
        __syncthreads();

        float s[4][4];
        #pragma unroll
        for (int i = 0; i < 4; i++)
            #pragma unroll
            for (int jj = 0; jj < 4; jj++) s[i][jj] = 0.f;

        #pragma unroll 4
        for (int d = 0; d < 128; d++) {
            float4 a4 = *(float4*)&Qt[d * 68 + 4 * ty];
            float4 b4 = *(float4*)&Kt[d * 68 + 4 * tx];
            float av[4] = {a4.x, a4.y, a4.z, a4.w};
            float bv[4] = {b4.x, b4.y, b4.z, b4.w};
            #pragma unroll
            for (int i = 0; i < 4; i++)
                #pragma unroll
                for (int jj = 0; jj < 4; jj++)
                    s[i][jj] = fmaf(av[i], bv[jj], s[i][jj]);
        }

        const bool diag = (j == qt);
        #pragma unroll
        for (int i = 0; i < 4; i++)
            #pragma unroll
            for (int jj = 0; jj < 4; jj++) {
                float val = s[i][jj] * scale;
                if (diag && (k0 + 4 * tx + jj > q0 + 4 * ty + i)) val = -1e30f;
                s[i][jj] = val;
            }

        #pragma unroll
        for (int i = 0; i < 4; i++) {
            float mloc = fmaxf(fmaxf(s[i][0], s[i][1]), fmaxf(s[i][2], s[i][3]));
            #pragma unroll
            for (int off = 8; off >= 1; off >>= 1)
                mloc = fmaxf(mloc, __shfl_xor_sync(0xffffffffu, mloc, off, 16));
            float mnew  = fmaxf(mrow[i], mloc);
            float alpha = __expf(mrow[i] - mnew);
            float psum = 0.f;
            #pragma unroll
            for (int jj = 0; jj < 4; jj++) {
                float p = __expf(s[i][jj] - mnew);
                s[i][jj] = p;
                psum += p;
            }
            #pragma unroll
            for (int off = 8; off >= 1; off >>= 1)
                psum += __shfl_xor_sync(0xffffffffu, psum, off, 16);
            lrow[i] = lrow[i] * alpha + psum;
            mrow[i] = mnew;
            #pragma unroll
            for (int c = 0; c < 8; c++) o[i][c] *= alpha;
            #pragma unroll
            for (int jj = 0; jj < 4; jj++)
                Ps[(4 * ty + i) * 65 + 4 * tx + jj] = s[i][jj];
        }
        __syncthreads();

        #pragma unroll 2
        for (int kk = 0; kk < 64; kk++) {
            float4 v0 = *(float4*)&Vs[kk * 128 + 8 * tx];
            float4 v1 = *(float4*)&Vs[kk * 128 + 8 * tx + 4];
            float pv[4];
            #pragma unroll
            for (int i = 0; i < 4; i++) pv[i] = Ps[(4 * ty + i) * 65 + kk];
            #pragma unroll
            for (int i = 0; i < 4; i++) {
                o[i][0] = fmaf(pv[i], v0.x, o[i][0]);
                o[i][1] = fmaf(pv[i], v0.y, o[i][1]);
                o[i][2] = fmaf(pv[i], v0.z, o[i][2]);
                o[i][3] = fmaf(pv[i], v0.w, o[i][3]);
                o[i][4] = fmaf(pv[i], v1.x, o[i][4]);
                o[i][5] = fmaf(pv[i], v1.y, o[i][5]);
                o[i][6] = fmaf(pv[i], v1.z, o[i][6]);
                o[i][7] = fmaf(pv[i], v1.w, o[i][7]);
            }
        }
    }

    // Epilogue: normalize, split to bf16 hi/lo for the dense HMMA GEMM
    #pragma unroll
    for (int i = 0; i < 4; i++) {
        float inv = 1.f / lrow[i];
        int row = q0 + 4 * ty + i;
        size_t base = (size_t)row * Q_SZ + h * HD + 8 * tx;
        #pragma unroll
        for (int c = 0; c < 8; c += 2) {
            float v0 = o[i][c] * inv, v1 = o[i][c + 1] * inv;
            __nv_bfloat16 h0 = __float2bfloat16(v0);
            __nv_bfloat16 h1 = __float2bfloat16(v1);
            __nv_bfloat162 hv; hv.x = h0; hv.y = h1;
            __nv_bfloat162 lv;
            lv.x = __float2bfloat16(v0 - __bfloat162float(h0));
            lv.y = __float2bfloat16(v1 - __bfloat162float(h1));
            *(__nv_bfloat162*)&out_hi[base + c] = hv;
            *(__nv_bfloat162*)&out_lo[base + c] = lv;
        }
    }
}

// ===========================================================================
extern "C" void kernel_launch(void* const* d_in, const int* in_sizes, int n_in,
                              void* d_out, int out_size)
{
    const float* hidden  = (const float*)d_in[0];
    const float* cosb    = (const float*)d_in[1];
    const float* sinb    = (const float*)d_in[2];
    const float* W_qkv   = (const float*)d_in[3];
    const float* b_qkv   = (const float*)d_in[4];
    const float* W_dense = (const float*)d_in[5];
    float* out = (float*)d_out;

    float* qkv;   cudaGetSymbolAddress((void**)&qkv,   g_qkv);
    __nv_bfloat16 *Ah_hi, *Ah_lo, *Wq_hi, *Wq_lo, *Wd_hi, *Wd_lo, *at_hi, *at_lo;
    cudaGetSymbolAddress((void**)&Ah_hi, g_Ah_hi);
    cudaGetSymbolAddress((void**)&Ah_lo, g_Ah_lo);
    cudaGetSymbolAddress((void**)&Wq_hi, g_Wq_hi);
    cudaGetSymbolAddress((void**)&Wq_lo, g_Wq_lo);
    cudaGetSymbolAddress((void**)&Wd_hi, g_Wd_hi);
    cudaGetSymbolAddress((void**)&Wd_lo, g_Wd_lo);
    cudaGetSymbolAddress((void**)&at_hi, g_at_hi);
    cudaGetSymbolAddress((void**)&at_lo, g_at_lo);

    cudaFuncSetAttribute(hmma_gemm, cudaFuncAttributeMaxDynamicSharedMemorySize, GEMM_SMEM);
    cudaFuncSetAttribute(flash_kernel, cudaFuncAttributeMaxDynamicSharedMemorySize, FL_SMEM_BYTES);

    // Prep: splits & transposed weight splits
    {
        int n4 = T_SEQ * HID / 4;
        split_kernel<<<(n4 + 255) / 256, 256>>>((const float4*)hidden, Ah_hi, Ah_lo, n4);
    }
    {
        dim3 grid(QKV_OUT / 32, HID / 32), blk(32, 8);
        transpose_split_kernel<<<grid, blk>>>(W_qkv, Wq_hi, Wq_lo, HID, QKV_OUT);
    }
    {
        dim3 grid(HID / 32, Q_SZ / 32), blk(32, 8);
        transpose_split_kernel<<<grid, blk>>>(W_dense, Wd_hi, Wd_lo, Q_SZ, HID);
    }

    // 1) QKV projection (HMMA bf16x3) + bias
    {
        dim3 grid(QKV_OUT / 128, T_SEQ / 128);
        hmma_gemm<<<grid, 256, GEMM_SMEM>>>(Ah_hi, Ah_lo, Wq_hi, Wq_lo, b_qkv, qkv,
                                            T_SEQ, QKV_OUT, HID);
    }

    // 2) RoPE
    {
        int total = T_SEQ * (NQH + NKVH) * ROPE_PAIRS;
        rope_kernel<<<(total + 255) / 256, 256>>>(qkv, cosb, sinb);
    }

    // 3) Flash attention (fp32 compute, bf16 hi/lo output)
    {
        dim3 grid(T_SEQ / 64, NQH);
        flash_kernel<<<grid, 256, FL_SMEM_BYTES>>>(qkv, at_hi, at_lo);
    }

    // 4) Dense projection (HMMA bf16x3)
    {
        dim3 grid(HID / 128, T_SEQ / 128);
        hmma_gemm<<<grid, 256, GEMM_SMEM>>>(at_hi, at_lo, Wd_hi, Wd_lo, nullptr, out,
                                            T_SEQ, HID, Q_SZ);
    }
}

// round 4
// speedup vs baseline: 2.3550x; 1.5899x over previous
#include <cuda_runtime.h>
#include <cuda_bf16.h>
#include <cstdint>

// ===========================================================================
// Problem constants
// ===========================================================================
#define T_SEQ   2048
#define HID     4096
#define NQH     32
#define NKVH    2
#define HD      128
#define QKV_OUT ((NQH + 2*NKVH) * HD)   // 4608
#define Q_SZ    (NQH * HD)              // 4096
#define KV_SZ   (NKVH * HD)             // 256
#define ROPE_PAIRS 32

// ===========================================================================
// Scratch
// ===========================================================================
__device__ float         g_qkv [T_SEQ * QKV_OUT];
__device__ __nv_bfloat16 g_Ah_hi[T_SEQ * HID];
__device__ __nv_bfloat16 g_Ah_lo[T_SEQ * HID];
__device__ __nv_bfloat16 g_Wq_hi[QKV_OUT * HID];
__device__ __nv_bfloat16 g_Wq_lo[QKV_OUT * HID];
__device__ __nv_bfloat16 g_Wd_hi[HID * Q_SZ];
__device__ __nv_bfloat16 g_Wd_lo[HID * Q_SZ];
__device__ __nv_bfloat16 g_at_hi[T_SEQ * Q_SZ];
__device__ __nv_bfloat16 g_at_lo[T_SEQ * Q_SZ];

// ===========================================================================
// Helpers
// ===========================================================================
__device__ __forceinline__ uint32_t smem_u32(const void* p) {
    uint32_t a;
    asm("{ .reg .u64 t; cvta.to.shared.u64 t, %1; cvt.u32.u64 %0, t; }"
        : "=r"(a) : "l"(p));
    return a;
}
__device__ __forceinline__ void cpa16(uint32_t dst, const void* src) {
    asm volatile("cp.async.cg.shared.global [%0], [%1], 16;" :: "r"(dst), "l"(src));
}
#define CP_COMMIT() asm volatile("cp.async.commit_group;" ::: "memory")
#define CP_WAIT(n)  asm volatile("cp.async.wait_group %0;" :: "n"(n) : "memory")

__device__ __forceinline__ void ldm_x4(uint32_t* r, uint32_t addr) {
    asm volatile("ldmatrix.sync.aligned.m8n8.x4.shared.b16 {%0,%1,%2,%3}, [%4];"
                 : "=r"(r[0]), "=r"(r[1]), "=r"(r[2]), "=r"(r[3]) : "r"(addr));
}
__device__ __forceinline__ void ldm_x2(uint32_t* r, uint32_t addr) {
    asm volatile("ldmatrix.sync.aligned.m8n8.x2.shared.b16 {%0,%1}, [%2];"
                 : "=r"(r[0]), "=r"(r[1]) : "r"(addr));
}
__device__ __forceinline__ void mma_bf16(float* c, const uint32_t* a, const uint32_t* b) {
    asm volatile(
        "mma.sync.aligned.m16n8k16.row.col.f32.bf16.bf16.f32 "
        "{%0,%1,%2,%3}, {%4,%5,%6,%7}, {%8,%9}, {%0,%1,%2,%3};"
        : "+f"(c[0]), "+f"(c[1]), "+f"(c[2]), "+f"(c[3])
        : "r"(a[0]), "r"(a[1]), "r"(a[2]), "r"(a[3]), "r"(b[0]), "r"(b[1]));
}
__device__ __forceinline__ uint32_t pk2(float lo, float hi) {
    __nv_bfloat162 t = __floats2bfloat162_rn(lo, hi);
    return *reinterpret_cast<uint32_t*>(&t);
}
__device__ __forceinline__ void split_pair(float x, float y, uint32_t& hp, uint32_t& lp) {
    float hx = __bfloat162float(__float2bfloat16(x));
    float hy = __bfloat162float(__float2bfloat16(y));
    hp = pk2(hx, hy);
    lp = pk2(x - hx, y - hy);
}

// ===========================================================================
// Prep kernels
// ===========================================================================
__global__ __launch_bounds__(256)
void split_kernel(const float4* __restrict__ X, __nv_bfloat16* __restrict__ hi,
                  __nv_bfloat16* __restrict__ lo, int n4)
{
    int i = blockIdx.x * blockDim.x + threadIdx.x;
    if (i >= n4) return;
    float4 v = X[i];
    uint32_t h0, l0, h1, l1;
    split_pair(v.x, v.y, h0, l0);
    split_pair(v.z, v.w, h1, l1);
    ((uint32_t*)hi)[2*i]   = h0;
    ((uint32_t*)hi)[2*i+1] = h1;
    ((uint32_t*)lo)[2*i]   = l0;
    ((uint32_t*)lo)[2*i+1] = l1;
}

__global__ __launch_bounds__(256)
void transpose_split_kernel(const float* __restrict__ W,
                            __nv_bfloat16* __restrict__ hi,
                            __nv_bfloat16* __restrict__ lo, int K, int N)
{
    __shared__ float t[32][33];
    int n0 = blockIdx.x * 32, k0 = blockIdx.y * 32;
    int tx = threadIdx.x, ty = threadIdx.y;
    #pragma unroll
    for (int i = ty; i < 32; i += 8)
        t[i][tx] = W[(size_t)(k0 + i) * N + n0 + tx];
    __syncthreads();
    #pragma unroll
    for (int i = ty; i < 32; i += 8) {
        float v = t[tx][i];
        __nv_bfloat16 h = __float2bfloat16(v);
        size_t o = (size_t)(n0 + i) * K + k0 + tx;
        hi[o] = h;
        lo[o] = __float2bfloat16(v - __bfloat162float(h));
    }
}

// ===========================================================================
// HMMA bf16x3 GEMM, 2 CTAs/SM
// ===========================================================================
#define SA_BYTES   80
#define TILE_BYTES (128 * SA_BYTES)
#define STAGE_BYTES (4 * TILE_BYTES)
#define GEMM_SMEM   (2 * STAGE_BYTES)

__device__ __forceinline__ void issue_stage(uint32_t sbase,
        const __nv_bfloat16* __restrict__ Ahi, const __nv_bfloat16* __restrict__ Alo,
        const __nv_bfloat16* __restrict__ Bhi, const __nv_bfloat16* __restrict__ Blo,
        int m0, int n0, int K, int k0)
{
    const int tid = threadIdx.x;
    #pragma unroll
    for (int i = 0; i < 2; i++) {
        int c   = tid + i * 256;
        int r   = c >> 2;
        int seg = c & 3;
        uint32_t doff = r * SA_BYTES + seg * 16;
        size_t  ga = (size_t)(m0 + r) * K + k0 + seg * 8;
        size_t  gb = (size_t)(n0 + r) * K + k0 + seg * 8;
        cpa16(sbase + doff,                  &Ahi[ga]);
        cpa16(sbase + TILE_BYTES + doff,     &Alo[ga]);
        cpa16(sbase + 2 * TILE_BYTES + doff, &Bhi[gb]);
        cpa16(sbase + 3 * TILE_BYTES + doff, &Blo[gb]);
    }
    CP_COMMIT();
}

__global__ __launch_bounds__(256, 2)
void hmma_gemm(const __nv_bfloat16* __restrict__ Ahi, const __nv_bfloat16* __restrict__ Alo,
               const __nv_bfloat16* __restrict__ Bhi, const __nv_bfloat16* __restrict__ Blo,
               const float* __restrict__ bias, float* __restrict__ C,
               int M, int N, int K)
{
    extern __shared__ __align__(128) char sm_raw[];
    const uint32_t sbase = smem_u32(sm_raw);
    const int tid  = threadIdx.x;
    const int lane = tid & 31;
    const int warp = tid >> 5;
    const int wm   = (warp >> 2) * 64;
    const int wn   = (warp & 3) * 32;
    const int m0 = blockIdx.y * 128;
    const int n0 = blockIdx.x * 128;

    const uint32_t a_off = (uint32_t)(wm + (lane & 15)) * SA_BYTES + ((lane >> 4) * 8) * 2;
    const int bl = lane & 15;
    const uint32_t b_off = (uint32_t)(wn + (bl & 7)) * SA_BYTES + (((bl >> 3) & 1) * 8) * 2;

    float acc[4][4][4];
    #pragma unroll
    for (int i = 0; i < 4; i++)
        #pragma unroll
        for (int j = 0; j < 4; j++)
            #pragma unroll
            for (int c = 0; c < 4; c++) acc[i][j][c] = 0.f;

    issue_stage(sbase, Ahi, Alo, Bhi, Blo, m0, n0, K, 0);

    const int nch = K / 32;
    for (int j = 0; j < nch; j++) {
        const uint32_t sb = sbase + (j & 1) * STAGE_BYTES;
        if (j + 1 < nch) {
            issue_stage(sbase + ((j + 1) & 1) * STAGE_BYTES,
                        Ahi, Alo, Bhi, Blo, m0, n0, K, (j + 1) * 32);
            CP_WAIT(1);
        } else {
            CP_WAIT(0);
        }
        __syncthreads();

        const uint32_t aaddr = sb + a_off;
        const uint32_t baddr = sb + 2 * TILE_BYTES + b_off;
        #pragma unroll
        for (int kk = 0; kk < 2; kk++) {
            const uint32_t ko = kk * 32;
            uint32_t ah[4][4], al[4][4];
            #pragma unroll
            for (int mi = 0; mi < 4; mi++) {
                ldm_x4(ah[mi], aaddr + mi * (16 * SA_BYTES) + ko);
                ldm_x4(al[mi], aaddr + TILE_BYTES + mi * (16 * SA_BYTES) + ko);
            }
            #pragma unroll
            for (int ni = 0; ni < 4; ni++) {
                uint32_t bh[2], blo_[2];
                ldm_x2(bh,   baddr + ni * (8 * SA_BYTES) + ko);
                ldm_x2(blo_, baddr + TILE_BYTES + ni * (8 * SA_BYTES) + ko);
                #pragma unroll
                for (int mi = 0; mi < 4; mi++) {
                    mma_bf16(acc[mi][ni], ah[mi], bh);
                    mma_bf16(acc[mi][ni], ah[mi], blo_);
                    mma_bf16(acc[mi][ni], al[mi], bh);
                }
            }
        }
        __syncthreads();
    }

    const int g = lane >> 2;
    const int t2 = (lane & 3) * 2;
    #pragma unroll
    for (int mi = 0; mi < 4; mi++) {
        #pragma unroll
        for (int ni = 0; ni < 4; ni++) {
            int row = m0 + wm + mi * 16 + g;
            int col = n0 + wn + ni * 8 + t2;
            float b0 = bias ? bias[col]     : 0.f;
            float b1 = bias ? bias[col + 1] : 0.f;
            float2 v0 = make_float2(acc[mi][ni][0] + b0, acc[mi][ni][1] + b1);
            float2 v1 = make_float2(acc[mi][ni][2] + b0, acc[mi][ni][3] + b1);
            *(float2*)&C[(size_t)row * N + col]       = v0;
            *(float2*)&C[(size_t)(row + 8) * N + col] = v1;
        }
    }
}

// ===========================================================================
// RoPE
// ===========================================================================
__global__ __launch_bounds__(256)
void rope_kernel(float* __restrict__ qkv, const float* __restrict__ cosb,
                 const float* __restrict__ sinb)
{
    int id = blockIdx.x * blockDim.x + threadIdx.x;
    const int total = T_SEQ * (NQH + NKVH) * ROPE_PAIRS;
    if (id >= total) return;
    int p    = id & 31;
    int head = (id >> 5) % (NQH + NKVH);
    int t    = id / ((NQH + NKVH) * ROPE_PAIRS);

    int base = (head < NQH) ? head * HD : Q_SZ + (head - NQH) * HD;
    float* x = qkv + (size_t)t * QKV_OUT + base;
    float c = cosb[t * 64 + p];
    float s = sinb[t * 64 + p];
    float x0 = x[2 * p];
    float x1 = x[2 * p + 1];
    x[2 * p]     = x0 * c - x1 * s;
    x[2 * p + 1] = x1 * c + x0 * s;
}

// ===========================================================================
// Flash attention, HMMA bf16x3. BQ=128, BK=64, 8 warps (warp owns 16 q-rows).
// smem (bf16 elems): Qhi[128][136], Qlo, Khi[64][136], Klo, Vthi[128][72], Vtlo
// ===========================================================================
#define FQ_STR 136          // Q/K row stride (bf16): 272B, conflict-free ldmatrix
#define FV_STR 72           // Vt row stride: 144B
#define EO_QHI 0
#define EO_QLO (128 * FQ_STR)                  // 17408
#define EO_KHI (2 * 128 * FQ_STR)              // 34816
#define EO_KLO (EO_KHI + 64 * FQ_STR)          // 43520
#define EO_VHI (EO_KLO + 64 * FQ_STR)          // 52224
#define EO_VLO (EO_VHI + 128 * FV_STR)         // 61440
#define FL_SMEM_BYTES ((EO_VLO + 128 * FV_STR) * 2)   // 141312

__global__ __launch_bounds__(256, 1)
void flash_hmma(const float* __restrict__ qkv,
                __nv_bfloat16* __restrict__ out_hi,
                __nv_bfloat16* __restrict__ out_lo)
{
    extern __shared__ __align__(128) __nv_bfloat16 fsp[];
    const uint32_t sb = smem_u32(fsp);

    const int qt = gridDim.x - 1 - blockIdx.x;   // heavy tiles first
    const int h  = blockIdx.y;
    const int q0 = qt * 128;
    const int kvh = h >> 4;
    const int tid  = threadIdx.x;
    const int lane = tid & 31;
    const int warp = tid >> 5;
    const int g  = lane >> 2;
    const int t4 = lane & 3;

    const int qcol = h * HD;
    const int kcol = Q_SZ + kvh * HD;
    const int vcol = Q_SZ + KV_SZ + kvh * HD;
    const float scale = 0.08838834764831845f;

    // ---- Load Q tile (128x128), split hi/lo ----
    #pragma unroll
    for (int t = 0; t < 16; t++) {
        int f  = tid + t * 256;           // 0..4095 float4 chunks
        int r  = f >> 5;
        int c4 = (f & 31) << 2;
        float4 v = *(const float4*)&qkv[(size_t)(q0 + r) * QKV_OUT + qcol + c4];
        uint32_t h0, l0, h1, l1;
        split_pair(v.x, v.y, h0, l0);
        split_pair(v.z, v.w, h1, l1);
        int e = r * FQ_STR + c4;
        *(uint32_t*)&fsp[EO_QHI + e]     = h0;
        *(uint32_t*)&fsp[EO_QHI + e + 2] = h1;
        *(uint32_t*)&fsp[EO_QLO + e]     = l0;
        *(uint32_t*)&fsp[EO_QLO + e + 2] = l1;
    }

    // O accumulators: 16 d-tiles of m16n8
    float oc[16][4];
    #pragma unroll
    for (int i = 0; i < 16; i++)
        #pragma unroll
        for (int c = 0; c < 4; c++) oc[i][c] = 0.f;
    float m0 = -1e30f, m1 = -1e30f, l0 = 0.f, l1 = 0.f;

    // ldmatrix base offsets (bytes)
    const uint32_t qa_off = (uint32_t)(16 * warp + (lane & 15)) * (FQ_STR * 2)
                          + ((lane >> 4) * 8) * 2;
    const int bl = lane & 15;
    const uint32_t kb_row = (uint32_t)(bl & 7);
    const uint32_t kb_ko  = ((bl >> 3) & 1) * 16;

    const int niters = 2 * qt + 2;
    for (int j = 0; j < niters; j++) {
        const int k0 = j * 64;
        __syncthreads();
        // ---- Load K (64x128) and V transposed, split hi/lo ----
        #pragma unroll
        for (int t = 0; t < 8; t++) {
            int f  = tid + t * 256;       // 0..2047
            int r  = f >> 5;
            int c4 = (f & 31) << 2;
            float4 kv4 = *(const float4*)&qkv[(size_t)(k0 + r) * QKV_OUT + kcol + c4];
            uint32_t h0_, l0_, h1_, l1_;
            split_pair(kv4.x, kv4.y, h0_, l0_);
            split_pair(kv4.z, kv4.w, h1_, l1_);
            int e = r * FQ_STR + c4;
            *(uint32_t*)&fsp[EO_KHI + e]     = h0_;
            *(uint32_t*)&fsp[EO_KHI + e + 2] = h1_;
            *(uint32_t*)&fsp[EO_KLO + e]     = l0_;
            *(uint32_t*)&fsp[EO_KLO + e + 2] = l1_;

            float4 vv = *(const float4*)&qkv[(size_t)(k0 + r) * QKV_OUT + vcol + c4];
            float vf[4] = {vv.x, vv.y, vv.z, vv.w};
            #pragma unroll
            for (int jj = 0; jj < 4; jj++) {
                float hv = __bfloat162float(__float2bfloat16(vf[jj]));
                fsp[EO_VHI + (c4 + jj) * FV_STR + r] = __float2bfloat16(vf[jj]);
                fsp[EO_VLO + (c4 + jj) * FV_STR + r] = __float2bfloat16(vf[jj] - hv);
            }
        }
        __syncthreads();

        // ---- S = Q @ K^T (bf16x3), per-warp 16x64 ----
        float sc[8][4];
        #pragma unroll
        for (int ni = 0; ni < 8; ni++)
            #pragma unroll
            for (int c = 0; c < 4; c++) sc[ni][c] = 0.f;

        #pragma unroll
        for (int ks = 0; ks < 8; ks++) {
            uint32_t qh[4], ql[4];
            ldm_x4(qh, sb + EO_QHI * 2 + qa_off + ks * 32);
            ldm_x4(ql, sb + EO_QLO * 2 + qa_off + ks * 32);
            #pragma unroll
            for (int ni = 0; ni < 8; ni++) {
                uint32_t kh[2], kl[2];
                uint32_t kb = (uint32_t)(8 * ni + kb_row) * (FQ_STR * 2) + kb_ko + ks * 32;
                ldm_x2(kh, sb + EO_KHI * 2 + kb);
                ldm_x2(kl, sb + EO_KLO * 2 + kb);
                mma_bf16(sc[ni], qh, kh);
                mma_bf16(sc[ni], qh, kl);
                mma_bf16(sc[ni], ql, kh);
            }
        }

        // ---- scale + causal mask ----
        const int row0 = q0 + 16 * warp + g;
        const int row1 = row0 + 8;
        const bool need_mask = (j >= 2 * qt);
        #pragma unroll
        for (int ni = 0; ni < 8; ni++) {
            int cb = k0 + 8 * ni + 2 * t4;
            sc[ni][0] *= scale; sc[ni][1] *= scale;
            sc[ni][2] *= scale; sc[ni][3] *= scale;
            if (need_mask) {
                if (cb     > row0) sc[ni][0] = -1e30f;
                if (cb + 1 > row0) sc[ni][1] = -1e30f;
                if (cb     > row1) sc[ni][2] = -1e30f;
                if (cb + 1 > row1) sc[ni][3] = -1e30f;
            }
        }

        // ---- online softmax (rows g and g+8; quad holds full row) ----
        float mx0 = -1e30f, mx1 = -1e30f;
        #pragma unroll
        for (int ni = 0; ni < 8; ni++) {
            mx0 = fmaxf(mx0, fmaxf(sc[ni][0], sc[ni][1]));
            mx1 = fmaxf(mx1, fmaxf(sc[ni][2], sc[ni][3]));
        }
        #pragma unroll
        for (int off = 1; off <= 2; off <<= 1) {
            mx0 = fmaxf(mx0, __shfl_xor_sync(0xffffffffu, mx0, off));
            mx1 = fmaxf(mx1, __shfl_xor_sync(0xffffffffu, mx1, off));
        }
        float mn0 = fmaxf(m0, mx0), mn1 = fmaxf(m1, mx1);
        float a0 = __expf(m0 - mn0), a1 = __expf(m1 - mn1);
        float s0 = 0.f, s1 = 0.f;
        #pragma unroll
        for (int ni = 0; ni < 8; ni++) {
            sc[ni][0] = __expf(sc[ni][0] - mn0);
            sc[ni][1] = __expf(sc[ni][1] - mn0);
            sc[ni][2] = __expf(sc[ni][2] - mn1);
            sc[ni][3] = __expf(sc[ni][3] - mn1);
            s0 += sc[ni][0] + sc[ni][1];
            s1 += sc[ni][2] + sc[ni][3];
        }
        #pragma unroll
        for (int off = 1; off <= 2; off <<= 1) {
            s0 += __shfl_xor_sync(0xffffffffu, s0, off);
            s1 += __shfl_xor_sync(0xffffffffu, s1, off);
        }
        l0 = l0 * a0 + s0;  m0 = mn0;
        l1 = l1 * a1 + s1;  m1 = mn1;
        #pragma unroll
        for (int nj = 0; nj < 16; nj++) {
            oc[nj][0] *= a0; oc[nj][1] *= a0;
            oc[nj][2] *= a1; oc[nj][3] *= a1;
        }

        // ---- O += P @ V (bf16x3); P A-frags straight from S C-frags ----
        #pragma unroll
        for (int ks = 0; ks < 4; ks++) {
            uint32_t ph[4], pl[4];
            split_pair(sc[2*ks][0],   sc[2*ks][1],   ph[0], pl[0]);
            split_pair(sc[2*ks][2],   sc[2*ks][3],   ph[1], pl[1]);
            split_pair(sc[2*ks+1][0], sc[2*ks+1][1], ph[2], pl[2]);
            split_pair(sc[2*ks+1][2], sc[2*ks+1][3], ph[3], pl[3]);
            #pragma unroll
            for (int nj = 0; nj < 16; nj++) {
                uint32_t vh[2], vl[2];
                uint32_t vb = (uint32_t)(8 * nj + kb_row) * (FV_STR * 2) + kb_ko + ks * 32;
                ldm_x2(vh, sb + EO_VHI * 2 + vb);
                ldm_x2(vl, sb + EO_VLO * 2 + vb);
                mma_bf16(oc[nj], ph, vh);
                mma_bf16(oc[nj], ph, vl);
                mma_bf16(oc[nj], pl, vh);
            }
        }
    }

    // ---- epilogue: normalize, split hi/lo, store ----
    float inv0 = 1.f / l0, inv1 = 1.f / l1;
    const int row0 = q0 + 16 * warp + g;
    #pragma unroll
    for (int nj = 0; nj < 16; nj++) {
        int col = h * HD + 8 * nj + 2 * t4;
        uint32_t hp, lp;
        split_pair(oc[nj][0] * inv0, oc[nj][1] * inv0, hp, lp);
        *(uint32_t*)&out_hi[(size_t)row0 * Q_SZ + col] = hp;
        *(uint32_t*)&out_lo[(size_t)row0 * Q_SZ + col] = lp;
        split_pair(oc[nj][2] * inv1, oc[nj][3] * inv1, hp, lp);
        *(uint32_t*)&out_hi[(size_t)(row0 + 8) * Q_SZ + col] = hp;
        *(uint32_t*)&out_lo[(size_t)(row0 + 8) * Q_SZ + col] = lp;
    }
}

// ===========================================================================
extern "C" void kernel_launch(void* const* d_in, const int* in_sizes, int n_in,
                              void* d_out, int out_size)
{
    const float* hidden  = (const float*)d_in[0];
    const float* cosb    = (const float*)d_in[1];
    const float* sinb    = (const float*)d_in[2];
    const float* W_qkv   = (const float*)d_in[3];
    const float* b_qkv   = (const float*)d_in[4];
    const float* W_dense = (const float*)d_in[5];
    float* out = (float*)d_out;

    float* qkv;   cudaGetSymbolAddress((void**)&qkv,   g_qkv);
    __nv_bfloat16 *Ah_hi, *Ah_lo, *Wq_hi, *Wq_lo, *Wd_hi, *Wd_lo, *at_hi, *at_lo;
    cudaGetSymbolAddress((void**)&Ah_hi, g_Ah_hi);
    cudaGetSymbolAddress((void**)&Ah_lo, g_Ah_lo);
    cudaGetSymbolAddress((void**)&Wq_hi, g_Wq_hi);
    cudaGetSymbolAddress((void**)&Wq_lo, g_Wq_lo);
    cudaGetSymbolAddress((void**)&Wd_hi, g_Wd_hi);
    cudaGetSymbolAddress((void**)&Wd_lo, g_Wd_lo);
    cudaGetSymbolAddress((void**)&at_hi, g_at_hi);
    cudaGetSymbolAddress((void**)&at_lo, g_at_lo);

    cudaFuncSetAttribute(hmma_gemm, cudaFuncAttributeMaxDynamicSharedMemorySize, GEMM_SMEM);
    cudaFuncSetAttribute(flash_hmma, cudaFuncAttributeMaxDynamicSharedMemorySize, FL_SMEM_BYTES);

    {
        int n4 = T_SEQ * HID / 4;
        split_kernel<<<(n4 + 255) / 256, 256>>>((const float4*)hidden, Ah_hi, Ah_lo, n4);
    }
    {
        dim3 grid(QKV_OUT / 32, HID / 32), blk(32, 8);
        transpose_split_kernel<<<grid, blk>>>(W_qkv, Wq_hi, Wq_lo, HID, QKV_OUT);
    }
    {
        dim3 grid(HID / 32, Q_SZ / 32), blk(32, 8);
        transpose_split_kernel<<<grid, blk>>>(W_dense, Wd_hi, Wd_lo, Q_SZ, HID);
    }

    // 1) QKV projection
    {
        dim3 grid(QKV_OUT / 128, T_SEQ / 128);
        hmma_gemm<<<grid, 256, GEMM_SMEM>>>(Ah_hi, Ah_lo, Wq_hi, Wq_lo, b_qkv, qkv,
                                            T_SEQ, QKV_OUT, HID);
    }
    // 2) RoPE
    {
        int total = T_SEQ * (NQH + NKVH) * ROPE_PAIRS;
        rope_kernel<<<(total + 255) / 256, 256>>>(qkv, cosb, sinb);
    }
    // 3) Flash attention (HMMA bf16x3)
    {
        dim3 grid(T_SEQ / 128, NQH);
        flash_hmma<<<grid, 256, FL_SMEM_BYTES>>>(qkv, at_hi, at_lo);
    }
    // 4) Dense projection
    {
        dim3 grid(HID / 128, T_SEQ / 128);
        hmma_gemm<<<grid, 256, GEMM_SMEM>>>(at_hi, at_lo, Wd_hi, Wd_lo, nullptr, out,
                                            T_SEQ, HID, Q_SZ);
    }
}

// round 5
// speedup vs baseline: 3.7883x; 1.6086x over previous
#include <cuda_runtime.h>
#include <cuda_fp16.h>
#include <cstdint>

// ===========================================================================
// Problem constants
// ===========================================================================
#define T_SEQ   2048
#define HID     4096
#define NQH     32
#define NKVH    2
#define HD      128
#define QKV_OUT ((NQH + 2*NKVH) * HD)   // 4608
#define Q_SZ    (NQH * HD)              // 4096
#define KV_SZ   (NKVH * HD)             // 256

// ===========================================================================
// Scratch
// ===========================================================================
__device__ float   g_qkv [T_SEQ * QKV_OUT];      // fp32 QKV GEMM output
__device__ __half  g_Ah  [T_SEQ * HID];          // hidden fp16
__device__ __half  g_Wq_hi[QKV_OUT * HID];       // W_qkv^T  [N,K] hi/lo
__device__ __half  g_Wq_lo[QKV_OUT * HID];
__device__ __half  g_Wd_hi[HID * Q_SZ];          // W_dense^T [N,K] hi/lo
__device__ __half  g_Wd_lo[HID * Q_SZ];
__device__ __half  g_Q   [T_SEQ * Q_SZ];         // roped Q fp16
__device__ __half  g_Kh  [T_SEQ * KV_SZ];        // roped K fp16 hi/lo
__device__ __half  g_Kl  [T_SEQ * KV_SZ];
__device__ __half  g_Vth [NKVH * HD * T_SEQ];    // V transposed [kvh*128+d][t]
__device__ __half  g_Vtl [NKVH * HD * T_SEQ];
__device__ __half  g_at  [T_SEQ * Q_SZ];         // attn output fp16

// ===========================================================================
// Helpers
// ===========================================================================
__device__ __forceinline__ uint32_t smem_u32(const void* p) {
    uint32_t a;
    asm("{ .reg .u64 t; cvta.to.shared.u64 t, %1; cvt.u32.u64 %0, t; }"
        : "=r"(a) : "l"(p));
    return a;
}
__device__ __forceinline__ void cpa16(uint32_t dst, const void* src) {
    asm volatile("cp.async.cg.shared.global [%0], [%1], 16;" :: "r"(dst), "l"(src));
}
#define CP_COMMIT() asm volatile("cp.async.commit_group;" ::: "memory")
#define CP_WAIT(n)  asm volatile("cp.async.wait_group %0;" :: "n"(n) : "memory")

__device__ __forceinline__ void ldm_x4(uint32_t* r, uint32_t addr) {
    asm volatile("ldmatrix.sync.aligned.m8n8.x4.shared.b16 {%0,%1,%2,%3}, [%4];"
                 : "=r"(r[0]), "=r"(r[1]), "=r"(r[2]), "=r"(r[3]) : "r"(addr));
}
__device__ __forceinline__ void ldm_x2(uint32_t* r, uint32_t addr) {
    asm volatile("ldmatrix.sync.aligned.m8n8.x2.shared.b16 {%0,%1}, [%2];"
                 : "=r"(r[0]), "=r"(r[1]) : "r"(addr));
}
__device__ __forceinline__ void mma_f16(float* c, const uint32_t* a, const uint32_t* b) {
    asm volatile(
        "mma.sync.aligned.m16n8k16.row.col.f32.f16.f16.f32 "
        "{%0,%1,%2,%3}, {%4,%5,%6,%7}, {%8,%9}, {%0,%1,%2,%3};"
        : "+f"(c[0]), "+f"(c[1]), "+f"(c[2]), "+f"(c[3])
        : "r"(a[0]), "r"(a[1]), "r"(a[2]), "r"(a[3]), "r"(b[0]), "r"(b[1]));
}
__device__ __forceinline__ uint32_t pkh2(float x, float y) {
    __half2 t = __floats2half2_rn(x, y);
    return *reinterpret_cast<uint32_t*>(&t);
}

// ===========================================================================
// Prep kernels
// ===========================================================================
__global__ __launch_bounds__(256)
void tohalf_kernel(const float4* __restrict__ X, __half* __restrict__ H, int n4)
{
    int i = blockIdx.x * blockDim.x + threadIdx.x;
    if (i >= n4) return;
    float4 v = X[i];
    ((uint32_t*)H)[2*i]   = pkh2(v.x, v.y);
    ((uint32_t*)H)[2*i+1] = pkh2(v.z, v.w);
}

// W [K,N] row-major -> out [N,K] fp16 hi/lo
__global__ __launch_bounds__(256)
void transpose_split_kernel(const float* __restrict__ W,
                            __half* __restrict__ hi,
                            __half* __restrict__ lo, int K, int N)
{
    __shared__ float t[32][33];
    int n0 = blockIdx.x * 32, k0 = blockIdx.y * 32;
    int tx = threadIdx.x, ty = threadIdx.y;
    #pragma unroll
    for (int i = ty; i < 32; i += 8)
        t[i][tx] = W[(size_t)(k0 + i) * N + n0 + tx];
    __syncthreads();
    #pragma unroll
    for (int i = ty; i < 32; i += 8) {
        float v = t[tx][i];
        __half h = __float2half_rn(v);
        size_t o = (size_t)(n0 + i) * K + k0 + tx;
        hi[o] = h;
        lo[o] = __float2half_rn(v - __half2float(h));
    }
}

// ===========================================================================
// RoPE + split + layout prep for flash.
// Reads g_qkv fp32, writes gQ (fp16), gK hi/lo, gVt hi/lo (transposed).
// ===========================================================================
__global__ __launch_bounds__(256)
void rope_split_kernel(const float* __restrict__ qkv,
                       const float* __restrict__ cosb,
                       const float* __restrict__ sinb)
{
    int id = blockIdx.x * blockDim.x + threadIdx.x;
    if (id >= T_SEQ * (QKV_OUT / 4)) return;
    int t   = id / (QKV_OUT / 4);
    int col = (id % (QKV_OUT / 4)) * 4;
    float4 v = *(const float4*)&qkv[(size_t)t * QKV_OUT + col];

    if (col < Q_SZ + KV_SZ) {                // q or k: rope on first 64 dims
        int d = col & 127;
        if (d < 64) {
            int p = d >> 1;                  // pairs p, p+1 (p <= 30)
            float c0 = cosb[t * 64 + p],     s0 = sinb[t * 64 + p];
            float c1 = cosb[t * 64 + p + 1], s1 = sinb[t * 64 + p + 1];
            float x0 = v.x, x1 = v.y, x2 = v.z, x3 = v.w;
            v.x = x0 * c0 - x1 * s0;  v.y = x1 * c0 + x0 * s0;
            v.z = x2 * c1 - x3 * s1;  v.w = x3 * c1 + x2 * s1;
        }
    }

    if (col < Q_SZ) {
        uint32_t* dst = (uint32_t*)&g_Q[(size_t)t * Q_SZ + col];
        dst[0] = pkh2(v.x, v.y);
        dst[1] = pkh2(v.z, v.w);
    } else if (col < Q_SZ + KV_SZ) {
        int kc = col - Q_SZ;                 // 0..255
        float f[4] = {v.x, v.y, v.z, v.w};
        __half h[4], l[4];
        #pragma unroll
        for (int i = 0; i < 4; i++) {
            h[i] = __float2half_rn(f[i]);
            l[i] = __float2half_rn(f[i] - __half2float(h[i]));
        }
        *(uint32_t*)&g_Kh[(size_t)t * KV_SZ + kc]     = pkh2(__half2float(h[0]), __half2float(h[1]));
        *(uint32_t*)&g_Kh[(size_t)t * KV_SZ + kc + 2] = pkh2(__half2float(h[2]), __half2float(h[3]));
        *(uint32_t*)&g_Kl[(size_t)t * KV_SZ + kc]     = pkh2(__half2float(l[0]), __half2float(l[1]));
        *(uint32_t*)&g_Kl[(size_t)t * KV_SZ + kc + 2] = pkh2(__half2float(l[2]), __half2float(l[3]));
    } else {
        int vc = col - (Q_SZ + KV_SZ);       // 0..255 = kvh*128 + d
        float f[4] = {v.x, v.y, v.z, v.w};
        #pragma unroll
        for (int i = 0; i < 4; i++) {
            __half h = __float2half_rn(f[i]);
            g_Vth[(size_t)(vc + i) * T_SEQ + t] = h;
            g_Vtl[(size_t)(vc + i) * T_SEQ + t] = __float2half_rn(f[i] - __half2float(h));
        }
    }
}

// ===========================================================================
// HMMA fp16 2-term GEMM: C = A[M,K] @ (Bhi+Blo)^T, [N,K] K-major.
// CTA 128x128, BK=32, 8 warps (64x32 warp tile), 3-stage cp.async, 2 CTA/SM.
// Stage: A[128][40], Bhi[128][40], Blo[128][40] fp16 (80B row stride).
// ===========================================================================
#define SA_BYTES    80
#define TILE_BYTES  (128 * SA_BYTES)        // 10240
#define STAGE_BYTES (3 * TILE_BYTES)        // 30720
#define GEMM_SMEM   (3 * STAGE_BYTES)       // 92160

__device__ __forceinline__ void issue_stage(uint32_t sbase,
        const __half* __restrict__ A,
        const __half* __restrict__ Bhi, const __half* __restrict__ Blo,
        int m0, int n0, int K, int k0)
{
    const int tid = threadIdx.x;
    #pragma unroll
    for (int i = 0; i < 2; i++) {
        int c   = tid + i * 256;            // 0..511
        int r   = c >> 2;
        int seg = c & 3;
        uint32_t doff = r * SA_BYTES + seg * 16;
        size_t  ga = (size_t)(m0 + r) * K + k0 + seg * 8;
        size_t  gb = (size_t)(n0 + r) * K + k0 + seg * 8;
        cpa16(sbase + doff,                  &A[ga]);
        cpa16(sbase + TILE_BYTES + doff,     &Bhi[gb]);
        cpa16(sbase + 2 * TILE_BYTES + doff, &Blo[gb]);
    }
    CP_COMMIT();
}

__global__ __launch_bounds__(256, 2)
void hmma_gemm(const __half* __restrict__ A,
               const __half* __restrict__ Bhi, const __half* __restrict__ Blo,
               const float* __restrict__ bias, float* __restrict__ C,
               int M, int N, int K)
{
    extern __shared__ __align__(128) char sm_raw[];
    const uint32_t sbase = smem_u32(sm_raw);
    const int tid  = threadIdx.x;
    const int lane = tid & 31;
    const int warp = tid >> 5;
    const int wm   = (warp >> 2) * 64;
    const int wn   = (warp & 3) * 32;
    const int m0 = blockIdx.y * 128;
    const int n0 = blockIdx.x * 128;

    const uint32_t a_off = (uint32_t)(wm + (lane & 15)) * SA_BYTES + ((lane >> 4) * 8) * 2;
    const int bl = lane & 15;
    const uint32_t b_off = (uint32_t)(wn + (bl & 7)) * SA_BYTES + (((bl >> 3) & 1) * 8) * 2;

    float acc[4][4][4];
    #pragma unroll
    for (int i = 0; i < 4; i++)
        #pragma unroll
        for (int j = 0; j < 4; j++)
            #pragma unroll
            for (int c = 0; c < 4; c++) acc[i][j][c] = 0.f;

    const int nch = K / 32;
    issue_stage(sbase,               A, Bhi, Blo, m0, n0, K, 0);
    issue_stage(sbase + STAGE_BYTES, A, Bhi, Blo, m0, n0, K, 32);

    for (int j = 0; j < nch; j++) {
        if (j + 1 < nch) { CP_WAIT(1); } else { CP_WAIT(0); }
        __syncthreads();
        if (j + 2 < nch)
            issue_stage(sbase + ((j + 2) % 3) * STAGE_BYTES,
                        A, Bhi, Blo, m0, n0, K, (j + 2) * 32);

        const uint32_t sb = sbase + (j % 3) * STAGE_BYTES;
        const uint32_t aaddr = sb + a_off;
        const uint32_t baddr = sb + TILE_BYTES + b_off;
        #pragma unroll
        for (int kk = 0; kk < 2; kk++) {
            const uint32_t ko = kk * 32;
            uint32_t ah[4][4];
            #pragma unroll
            for (int mi = 0; mi < 4; mi++)
                ldm_x4(ah[mi], aaddr + mi * (16 * SA_BYTES) + ko);
            #pragma unroll
            for (int ni = 0; ni < 4; ni++) {
                uint32_t bh[2], blo_[2];
                ldm_x2(bh,   baddr + ni * (8 * SA_BYTES) + ko);
                ldm_x2(blo_, baddr + TILE_BYTES + ni * (8 * SA_BYTES) + ko);
                #pragma unroll
                for (int mi = 0; mi < 4; mi++) {
                    mma_f16(acc[mi][ni], ah[mi], bh);
                    mma_f16(acc[mi][ni], ah[mi], blo_);
                }
            }
        }
    }

    const int g = lane >> 2;
    const int t2 = (lane & 3) * 2;
    #pragma unroll
    for (int mi = 0; mi < 4; mi++) {
        #pragma unroll
        for (int ni = 0; ni < 4; ni++) {
            int row = m0 + wm + mi * 16 + g;
            int col = n0 + wn + ni * 8 + t2;
            float b0 = bias ? bias[col]     : 0.f;
            float b1 = bias ? bias[col + 1] : 0.f;
            float2 v0 = make_float2(acc[mi][ni][0] + b0, acc[mi][ni][1] + b1);
            float2 v1 = make_float2(acc[mi][ni][2] + b0, acc[mi][ni][3] + b1);
            *(float2*)&C[(size_t)row * N + col]       = v0;
            *(float2*)&C[(size_t)(row + 8) * N + col] = v1;
        }
    }
}

// ===========================================================================
// Flash attention, fp16 2-term HMMA. BQ=128, BK=64, 8 warps.
// smem (fp16 elems): Qh[128][136]; 2 stages of {Kh[64][136], Kl[64][136],
//   Vth[128][72], Vtl[128][72]}.
// ===========================================================================
#define FQ_STR 136
#define FV_STR 72
#define FQ_ELEMS (128 * FQ_STR)                      // 17408
#define FST_K    (64 * FQ_STR)                       // 8704
#define FST_ELEMS (2 * FST_K + 2 * 128 * FV_STR)     // 35840
#define FL_SMEM_BYTES ((FQ_ELEMS + 2 * FST_ELEMS) * 2)  // 178176

__device__ __forceinline__ void flash_issue_kv(uint32_t stbase, int kvh, int k0)
{
    const int tid = threadIdx.x;
    // K hi/lo: 64 rows x 16 chunks each
    #pragma unroll
    for (int i = 0; i < 4; i++) {
        int c   = tid + i * 256;            // 0..1023
        int r   = c >> 4;
        int seg = c & 15;
        uint32_t off = r * (FQ_STR * 2) + seg * 16;
        size_t   gk  = (size_t)(k0 + r) * KV_SZ + kvh * HD + seg * 8;
        cpa16(stbase + off,              &g_Kh[gk]);
        cpa16(stbase + FST_K * 2 + off,  &g_Kl[gk]);
    }
    // Vt hi/lo: 128 rows x 8 chunks each
    #pragma unroll
    for (int i = 0; i < 4; i++) {
        int c   = tid + i * 256;            // 0..1023
        int d   = c >> 3;
        int seg = c & 7;
        uint32_t off = d * (FV_STR * 2) + seg * 16;
        size_t   gv  = (size_t)(kvh * HD + d) * T_SEQ + k0 + seg * 8;
        cpa16(stbase + 2 * FST_K * 2 + off,                   &g_Vth[gv]);
        cpa16(stbase + (2 * FST_K + 128 * FV_STR) * 2 + off,  &g_Vtl[gv]);
    }
    CP_COMMIT();
}

__global__ __launch_bounds__(256, 1)
void flash_hmma(__half* __restrict__ out)
{
    extern __shared__ __align__(128) __half fsp[];
    const uint32_t sb = smem_u32(fsp);

    const int qt = gridDim.x - 1 - blockIdx.x;   // heavy tiles first
    const int h  = blockIdx.y;
    const int q0 = qt * 128;
    const int kvh = h >> 4;
    const int tid  = threadIdx.x;
    const int lane = tid & 31;
    const int warp = tid >> 5;
    const int g  = lane >> 2;
    const int t4 = lane & 3;
    const float scale = 0.08838834764831845f;

    const int niters = 2 * qt + 2;

    // Prologue: Q tile + stage0 in group0; stage1 in group1.
    {
        #pragma unroll
        for (int i = 0; i < 8; i++) {
            int c   = tid + i * 256;        // 0..2047
            int r   = c >> 4;
            int seg = c & 15;
            uint32_t off = r * (FQ_STR * 2) + seg * 16;
            size_t   gq  = (size_t)(q0 + r) * Q_SZ + h * HD + seg * 8;
            cpa16(sb + off, &g_Q[gq]);
        }
        flash_issue_kv(sb + FQ_ELEMS * 2, kvh, 0);                 // group 0 (with Q)
        if (niters > 1)
            flash_issue_kv(sb + (FQ_ELEMS + FST_ELEMS) * 2, kvh, 64);  // group 1
    }

    float oc[16][4];
    #pragma unroll
    for (int i = 0; i < 16; i++)
        #pragma unroll
        for (int c = 0; c < 4; c++) oc[i][c] = 0.f;
    float m0 = -1e30f, m1 = -1e30f, l0 = 0.f, l1 = 0.f;

    const uint32_t qa_off = (uint32_t)(16 * warp + (lane & 15)) * (FQ_STR * 2)
                          + ((lane >> 4) * 8) * 2;
    const int bl = lane & 15;
    const uint32_t kb_row = (uint32_t)(bl & 7);
    const uint32_t kb_ko  = ((bl >> 3) & 1) * 16;

    for (int j = 0; j < niters; j++) {
        const int k0 = j * 64;
        if (j + 1 < niters) { CP_WAIT(1); } else { CP_WAIT(0); }
        __syncthreads();

        const uint32_t stb = sb + (FQ_ELEMS + (j & 1) * FST_ELEMS) * 2;
        const uint32_t kh_b = stb;
        const uint32_t kl_b = stb + FST_K * 2;
        const uint32_t vh_b = stb + 2 * FST_K * 2;
        const uint32_t vl_b = stb + (2 * FST_K + 128 * FV_STR) * 2;

        // ---- S = Q @ K^T (fp16 2-term) ----
        float sc[8][4];
        #pragma unroll
        for (int ni = 0; ni < 8; ni++)
            #pragma unroll
            for (int c = 0; c < 4; c++) sc[ni][c] = 0.f;

        #pragma unroll
        for (int ks = 0; ks < 8; ks++) {
            uint32_t qh[4];
            ldm_x4(qh, sb + qa_off + ks * 32);
            #pragma unroll
            for (int ni = 0; ni < 8; ni++) {
                uint32_t kh[2], kl[2];
                uint32_t kb = (uint32_t)(8 * ni + kb_row) * (FQ_STR * 2) + kb_ko + ks * 32;
                ldm_x2(kh, kh_b + kb);
                ldm_x2(kl, kl_b + kb);
                mma_f16(sc[ni], qh, kh);
                mma_f16(sc[ni], qh, kl);
            }
        }

        // ---- scale + causal mask ----
        const int row0 = q0 + 16 * warp + g;
        const int row1 = row0 + 8;
        const bool need_mask = (j >= 2 * qt);
        #pragma unroll
        for (int ni = 0; ni < 8; ni++) {
            int cb = k0 + 8 * ni + 2 * t4;
            sc[ni][0] *= scale; sc[ni][1] *= scale;
            sc[ni][2] *= scale; sc[ni][3] *= scale;
            if (need_mask) {
                if (cb     > row0) sc[ni][0] = -1e30f;
                if (cb + 1 > row0) sc[ni][1] = -1e30f;
                if (cb     > row1) sc[ni][2] = -1e30f;
                if (cb + 1 > row1) sc[ni][3] = -1e30f;
            }
        }

        // ---- online softmax ----
        float mx0 = -1e30f, mx1 = -1e30f;
        #pragma unroll
        for (int ni = 0; ni < 8; ni++) {
            mx0 = fmaxf(mx0, fmaxf(sc[ni][0], sc[ni][1]));
            mx1 = fmaxf(mx1, fmaxf(sc[ni][2], sc[ni][3]));
        }
        #pragma unroll
        for (int off = 1; off <= 2; off <<= 1) {
            mx0 = fmaxf(mx0, __shfl_xor_sync(0xffffffffu, mx0, off));
            mx1 = fmaxf(mx1, __shfl_xor_sync(0xffffffffu, mx1, off));
        }
        float mn0 = fmaxf(m0, mx0), mn1 = fmaxf(m1, mx1);
        float a0 = __expf(m0 - mn0), a1 = __expf(m1 - mn1);
        float s0 = 0.f, s1 = 0.f;
        #pragma unroll
        for (int ni = 0; ni < 8; ni++) {
            sc[ni][0] = __expf(sc[ni][0] - mn0);
            sc[ni][1] = __expf(sc[ni][1] - mn0);
            sc[ni][2] = __expf(sc[ni][2] - mn1);
            sc[ni][3] = __expf(sc[ni][3] - mn1);
            s0 += sc[ni][0] + sc[ni][1];
            s1 += sc[ni][2] + sc[ni][3];
        }
        #pragma unroll
        for (int off = 1; off <= 2; off <<= 1) {
            s0 += __shfl_xor_sync(0xffffffffu, s0, off);
            s1 += __shfl_xor_sync(0xffffffffu, s1, off);
        }
        l0 = l0 * a0 + s0;  m0 = mn0;
        l1 = l1 * a1 + s1;  m1 = mn1;
        #pragma unroll
        for (int nj = 0; nj < 16; nj++) {
            oc[nj][0] *= a0; oc[nj][1] *= a0;
            oc[nj][2] *= a1; oc[nj][3] *= a1;
        }

        // ---- O += P @ V (fp16 2-term; P A-frags from S C-frags) ----
        #pragma unroll
        for (int ks = 0; ks < 4; ks++) {
            uint32_t ph[4];
            ph[0] = pkh2(sc[2*ks][0],   sc[2*ks][1]);
            ph[1] = pkh2(sc[2*ks][2],   sc[2*ks][3]);
            ph[2] = pkh2(sc[2*ks+1][0], sc[2*ks+1][1]);
            ph[3] = pkh2(sc[2*ks+1][2], sc[2*ks+1][3]);
            #pragma unroll
            for (int nj = 0; nj < 16; nj++) {
                uint32_t vh[2], vl[2];
                uint32_t vb = (uint32_t)(8 * nj + kb_row) * (FV_STR * 2) + kb_ko + ks * 32;
                ldm_x2(vh, vh_b + vb);
                ldm_x2(vl, vl_b + vb);
                mma_f16(oc[nj], ph, vh);
                mma_f16(oc[nj], ph, vl);
            }
        }

        // Issue next stage (overwrites buffer j&1, free after this sync point)
        __syncthreads();
        if (j + 2 < niters)
            flash_issue_kv(sb + (FQ_ELEMS + (j & 1) * FST_ELEMS) * 2, kvh, (j + 2) * 64);
    }

    // ---- epilogue: normalize, fp16 store ----
    float inv0 = 1.f / l0, inv1 = 1.f / l1;
    const int row0 = q0 + 16 * warp + g;
    #pragma unroll
    for (int nj = 0; nj < 16; nj++) {
        int col = h * HD + 8 * nj + 2 * t4;
        *(uint32_t*)&out[(size_t)row0 * Q_SZ + col]       = pkh2(oc[nj][0] * inv0, oc[nj][1] * inv0);
        *(uint32_t*)&out[(size_t)(row0 + 8) * Q_SZ + col] = pkh2(oc[nj][2] * inv1, oc[nj][3] * inv1);
    }
}

// ===========================================================================
extern "C" void kernel_launch(void* const* d_in, const int* in_sizes, int n_in,
                              void* d_out, int out_size)
{
    const float* hidden  = (const float*)d_in[0];
    const float* cosb    = (const float*)d_in[1];
    const float* sinb    = (const float*)d_in[2];
    const float* W_qkv   = (const float*)d_in[3];
    const float* b_qkv   = (const float*)d_in[4];
    const float* W_dense = (const float*)d_in[5];
    float* out = (float*)d_out;

    float* qkv;  cudaGetSymbolAddress((void**)&qkv, g_qkv);
    __half *Ah, *Wq_hi, *Wq_lo, *Wd_hi, *Wd_lo, *at;
    cudaGetSymbolAddress((void**)&Ah,    g_Ah);
    cudaGetSymbolAddress((void**)&Wq_hi, g_Wq_hi);
    cudaGetSymbolAddress((void**)&Wq_lo, g_Wq_lo);
    cudaGetSymbolAddress((void**)&Wd_hi, g_Wd_hi);
    cudaGetSymbolAddress((void**)&Wd_lo, g_Wd_lo);
    cudaGetSymbolAddress((void**)&at,    g_at);

    cudaFuncSetAttribute(hmma_gemm, cudaFuncAttributeMaxDynamicSharedMemorySize, GEMM_SMEM);
    cudaFuncSetAttribute(flash_hmma, cudaFuncAttributeMaxDynamicSharedMemorySize, FL_SMEM_BYTES);

    // Prep
    {
        int n4 = T_SEQ * HID / 4;
        tohalf_kernel<<<(n4 + 255) / 256, 256>>>((const float4*)hidden, Ah, n4);
    }
    {
        dim3 grid(QKV_OUT / 32, HID / 32), blk(32, 8);
        transpose_split_kernel<<<grid, blk>>>(W_qkv, Wq_hi, Wq_lo, HID, QKV_OUT);
    }
    {
        dim3 grid(HID / 32, Q_SZ / 32), blk(32, 8);
        transpose_split_kernel<<<grid, blk>>>(W_dense, Wd_hi, Wd_lo, Q_SZ, HID);
    }

    // 1) QKV projection (fp16 2-term HMMA) + bias
    {
        dim3 grid(QKV_OUT / 128, T_SEQ / 128);
        hmma_gemm<<<grid, 256, GEMM_SMEM>>>(Ah, Wq_hi, Wq_lo, b_qkv, qkv,
                                            T_SEQ, QKV_OUT, HID);
    }
    // 2) RoPE + split + flash layout prep
    {
        int total = T_SEQ * (QKV_OUT / 4);
        rope_split_kernel<<<(total + 255) / 256, 256>>>(qkv, cosb, sinb);
    }
    // 3) Flash attention
    {
        dim3 grid(T_SEQ / 128, NQH);
        flash_hmma<<<grid, 256, FL_SMEM_BYTES>>>(at);
    }
    // 4) Dense projection
    {
        dim3 grid(HID / 128, T_SEQ / 128);
        hmma_gemm<<<grid, 256, GEMM_SMEM>>>(at, Wd_hi, Wd_lo, nullptr, out,
                                            T_SEQ, HID, Q_SZ);
    }
}